// round 16
// baseline (speedup 1.0000x reference)
#include <cuda_runtime.h>
#include <math.h>

#define NC   1000
#define NA   64
#define NBLK 33                      // 32 pp blocks + 1 omega block
#define FPSCALE 4398046511104.0f     // 2^42, exact in float

// Scratch + accumulators. __device__ globals (no allocation allowed).
// g_sum/g_key are ORDER-INDEPENDENT (integer add / max) => bit-deterministic.
// g_count and the accumulators self-reset each launch => graph replays work.
__device__ float g_pp[1024];
__device__ float g_som[128];
__device__ int   g_nm1;
__device__ unsigned long long g_sum = 0;  // sum(exp(pp)) in 2^-42 fixed point
__device__ unsigned long long g_key = 0;  // argmax(p0): (bits(p0)<<32)|(1023-row)
__device__ int   g_count = 0;

// ONE fused kernel, single wave (33 blocks <= 148 SMs), no spinning:
//   blocks 0..31 : pp rows (warp per row) + per-BLOCK combine -> 2 atomics.
//   block 32     : omega table (exact float recurrence) + underflow index.
//   every block  : prefetches p0 into registers before arrival.
//   last arrival : runs the lean solver (scalars pre-reduced, local t_j,
//                  one max-reduction).
__global__ __launch_bounds__(1024) void fused_kernel(const float* __restrict__ p0,
                                                     const float* __restrict__ P,
                                                     const float* __restrict__ W,
                                                     const float* __restrict__ omega,
                                                     float* __restrict__ out) {
    __shared__ float s_pe[32];                 // per-warp exp(pp) partials
    __shared__ unsigned long long s_pk[32];    // per-warp argmax keys
    __shared__ unsigned sb[4];
    __shared__ int   s_last;
    __shared__ float som[128];
    __shared__ float s_ppc;
    __shared__ int   b_t[32];
    __shared__ int   s_istar;

    const unsigned FULL = 0xffffffffu;
    int tid  = threadIdx.x;
    int lane = tid & 31;
    int wid  = tid >> 5;
    bool live = (tid < NC);

    // ---- prefetch p0 (every block) so the solver already holds it ----
    float p0v = live ? p0[tid] : -INFINITY;

    // ---- Phase 1: producer work ----
    if (blockIdx.x == 32) {
        if (tid < 128) {
            float w0 = omega[0];
            w0 = fminf(fmaxf(w0, 0.0f), 1.0f);
            float cur = w0;
            #pragma unroll
            for (int k = 0; k < 127; ++k)
                if (k < tid) cur -= 0.01f;         // exact float recurrence
            g_som[tid] = cur;
            unsigned b = __ballot_sync(FULL, (cur - 0.01f) < 0.001f);
            if (lane == 0) sb[wid] = b;
        }
        __syncthreads();
        if (tid == 0) {
            int nm1 = 127;                         // forced underflow index
            #pragma unroll
            for (int w = 0; w < 4; ++w)
                if (sb[w]) { nm1 = w * 32 + __ffs(sb[w]) - 1; break; }
            g_nm1 = nm1;
        }
    } else {
        int row = blockIdx.x * 32 + wid;           // warp per row
        if (row < NC) {
            const float2* w2 = reinterpret_cast<const float2*>(W + row * NA);
            const float2* p2 = reinterpret_cast<const float2*>(P + row * NA);
            float2 w = w2[lane];
            float2 p = p2[lane];
            float s = w.x * p.x + w.y * p.y;
            #pragma unroll
            for (int off = 16; off; off >>= 1)
                s += __shfl_down_sync(FULL, s, off);
            if (lane == 0) {
                g_pp[row] = s;
                s_pe[wid] = __expf(s);
                s_pk[wid] = ((unsigned long long)__float_as_uint(p0[row]) << 32)
                          | (unsigned long long)(1023 - row);  // bigger = smaller row
            }
        } else if (lane == 0) {
            s_pe[wid] = 0.0f;
            s_pk[wid] = 0ULL;
        }
        __syncthreads();
        if (tid == 0) {
            unsigned long long tot = 0, mk = 0;
            #pragma unroll
            for (int w = 0; w < 32; ++w) {
                tot += (unsigned long long)llrintf(s_pe[w] * FPSCALE); // exact int
                mk = (s_pk[w] > mk) ? s_pk[w] : mk;
            }
            atomicAdd(&g_sum, tot);   // ONE per block: ~30cyc total L2 serial
            atomicMax(&g_key, mk);
        }
    }
    __syncthreads();

    // ---- Arrival: elect the last block (single wave => no spinning) ----
    if (tid == 0) {
        __threadfence();                           // release all producer writes
        int old = atomicAdd(&g_count, 1);
        s_last = (old == NBLK - 1);
        if (s_last) g_count = 0;                   // reset for next replay
    }
    __syncthreads();
    if (!s_last) return;
    __threadfence();                               // acquire side

    // ================= Lean solver (R15 body) =================
    if (tid < 128) som[tid] = __ldcg(&g_som[tid]); // stage omega table to SMEM
    unsigned long long S = __ldcg(&g_sum);
    unsigned long long K = __ldcg(&g_key);
    int   nm1 = __ldcg(&g_nm1);
    float ppv = live ? __ldcg(&g_pp[tid]) : 0.0f;

    int   c   = 1023 - (int)(K & 1023u);
    float p0c = __uint_as_float((unsigned)(K >> 32));
    if (tid == c) s_ppc = ppv;                     // broadcast pp[c] via SMEM
    __syncthreads();                               // barrier A: som + s_ppc

    float sumexp = (float)S * (1.0f / FPSCALE);
    float inv    = 1.0f / sumexp;
    float qv     = __expf(ppv) * inv;
    float qc     = __expf(s_ppc) * inv;            // bitwise == owner's qv
    float w0     = som[0];

    // ---- Local exact stop index t_j (no sync) ----
    // Violation (j beats c): j<c needs vj >= vc ; j>c needs vj > vc.
    // d(w) = (1-w)A + wB, A = p0c-p0j > 0.  No crossover => t=0.  Else real
    // crossover theta = A/(A-B); float transition lies within +-1 step
    // (margin 0.01*(A-B) >> float noise): 5-point exact check from 2 steps
    // early resolves t exactly.  Capped at nm1 (forced underflow).
    int t = 0;
    if (live && tid != c) {
        float A = p0c - p0v;
        float B = qc  - qv;
        bool cross = (tid < c) ? (B <= 0.0f) : (B < 0.0f);
        if (cross) {
            float theta = A / (A - B);
            int ie = (int)ceilf((w0 - theta) * 100.0f);
            int s0 = ie - 2;
            if (s0 < 0) s0 = 0;
            if (s0 > nm1) s0 = nm1;
            t = nm1;                               // default: violates to end
            bool found = false;
            #pragma unroll
            for (int s = 0; s < 5; ++s) {
                int i = s0 + s;
                if (i > nm1) i = nm1;
                float cw   = som[i];               // SMEM, 29 cyc
                float onem = 1.0f - cw;
                float vc = onem * p0c + cw * qc;
                float vj = onem * p0v + cw * qv;
                bool viol = (tid < c) ? (vj >= vc) : (vj > vc);
                if (!found && !viol) { t = i; found = true; }
            }
        }
    }

    // ---- istar = max_j t_j : REDUX per warp, stage 2 on warp 0 ----
    {
        int m = __reduce_max_sync(FULL, t);
        if (lane == 0) b_t[wid] = m;
    }
    __syncthreads();                               // barrier B
    if (wid == 0) {
        int m = __reduce_max_sync(FULL, b_t[lane]);
        if (lane == 0) s_istar = m;
    }
    __syncthreads();                               // barrier C

    // ---- Output: p = (1-omega*) * p0 + omega* * q, shape (1, NC) ----
    float om = som[s_istar];                       // SMEM broadcast
    if (live)
        out[tid] = (1.0f - om) * p0v + om * qv;

    // ---- Reset accumulators for the next graph replay ----
    if (tid == 0) { g_sum = 0ULL; g_key = 0ULL; }
}

extern "C" void kernel_launch(void* const* d_in, const int* in_sizes, int n_in,
                              void* d_out, int out_size) {
    const float* p0 = (const float*)d_in[0];
    const float* P  = (const float*)d_in[1];
    const float* W  = (const float*)d_in[2];
    const float* om = (const float*)d_in[3];
    float* out = (float*)d_out;

    fused_kernel<<<NBLK, 1024>>>(p0, P, W, om, out);
}

// round 17
// speedup vs baseline: 1.0108x; 1.0108x over previous
#include <cuda_runtime.h>
#include <math.h>

#define NC 1000
#define NA 64
#define FPSCALE 4398046511104.0f   // 2^42, exact in float

// Scratch + cross-kernel accumulators. __device__ globals (no allocation).
// g_sum is ORDER-INDEPENDENT (integer add) => bit-deterministic; it self-
// resets in solve_kernel for graph replays.  g_key is plain-stored by one
// thread (no atomics needed).
__device__ float g_pp[1024];
__device__ float g_som[128];
__device__ int   g_nm1;
__device__ unsigned long long g_sum = 0;   // sum(exp(pp)) in 2^-42 fixed point
__device__ unsigned long long g_key;       // argmax(p0): (bits(p0)<<32)|(1023-row)

// Kernel 1: blocks 0..124: pp rows; per-WARP fire-and-forget sum-REDs only.
//           block 125:     omega table + underflow index + argmax(p0)
//                          (p0 loads issued first, hidden under the 508-cyc
//                           omega FADD chain; plain store of the key).
__global__ void pp_kernel(const float* __restrict__ W, const float* __restrict__ P,
                          const float* __restrict__ p0,
                          const float* __restrict__ omega) {
    const unsigned FULL = 0xffffffffu;
    int tid  = threadIdx.x;
    int lane = tid & 31;
    int wid  = tid >> 5;

    if (blockIdx.x == 125) {
        __shared__ unsigned sb[4];
        __shared__ float  red_v[8];
        __shared__ int    red_i[8];

        // ---- argmax(p0) loads first (overlap DRAM latency with FADD chain) --
        float pv[4];
        #pragma unroll
        for (int k = 0; k < 4; ++k) {
            int j = k * 256 + tid;
            pv[k] = (j < NC) ? p0[j] : -INFINITY;
        }

        // ---- omega table: exact float recurrence, predicated FADD chain ----
        if (tid < 128) {
            float w0 = omega[0];
            w0 = fminf(fmaxf(w0, 0.0f), 1.0f);
            float cur = w0;
            #pragma unroll
            for (int k = 0; k < 127; ++k)
                if (k < tid) cur -= 0.01f;
            g_som[tid] = cur;
            unsigned b = __ballot_sync(FULL, (cur - 0.01f) < 0.001f);
            if (lane == 0) sb[wid] = b;
        }

        // ---- local argmax (k ascending => ascending j: '>' keeps first) ----
        float av = -INFINITY;
        int   ai = 0x7fffffff;
        #pragma unroll
        for (int k = 0; k < 4; ++k) {
            int j = k * 256 + tid;
            if (pv[k] > av) { av = pv[k]; ai = j; }
        }
        #pragma unroll
        for (int off = 16; off; off >>= 1) {
            float ov = __shfl_down_sync(FULL, av, off);
            int   oi = __shfl_down_sync(FULL, ai, off);
            if (ov > av || (ov == av && oi < ai)) { av = ov; ai = oi; }
        }
        if (lane == 0) { red_v[wid] = av; red_i[wid] = ai; }
        __syncthreads();

        if (tid == 0) {
            // stage 2: combine 8 warp partials (first-index tie-break)
            float bv = -INFINITY;
            int   bi = 0x7fffffff;
            #pragma unroll
            for (int w = 0; w < 8; ++w) {
                float ov = red_v[w]; int oi = red_i[w];
                if (ov > bv || (ov == bv && oi < bi)) { bv = ov; bi = oi; }
            }
            g_key = ((unsigned long long)__float_as_uint(bv) << 32)
                  | (unsigned long long)(1023 - bi);      // plain store

            int nm1 = 127;                                // forced underflow idx
            #pragma unroll
            for (int w = 0; w < 4; ++w)
                if (sb[w]) { nm1 = w * 32 + __ffs(sb[w]) - 1; break; }
            g_nm1 = nm1;
        }
        return;
    }

    int row = (blockIdx.x * blockDim.x + tid) >> 5;   // rows 0..999 exactly
    const float2* w2 = reinterpret_cast<const float2*>(W + row * NA);
    const float2* p2 = reinterpret_cast<const float2*>(P + row * NA);
    float2 w = w2[lane];
    float2 p = p2[lane];
    float s = w.x * p.x + w.y * p.y;
    #pragma unroll
    for (int off = 16; off; off >>= 1)
        s += __shfl_down_sync(FULL, s, off);
    if (lane == 0) {
        g_pp[row] = s;
        // Single fire-and-forget RED per row (result discarded => REDG).
        // Integer add: order-independent => deterministic.
        atomicAdd(&g_sum, (unsigned long long)llrintf(__expf(s) * FPSCALE));
    }
}

// Kernel 2: minimal 1024-thread solver (R15 body, unchanged numerics).
//   Scalars pre-reduced by pp_kernel; som staged to SMEM; pp[c] broadcast by
//   thread c via SMEM.  3 barriers total.
__global__ __launch_bounds__(1024) void solve_kernel(const float* __restrict__ p0,
                                                     float* __restrict__ out) {
    __shared__ float som[128];
    __shared__ float s_ppc;
    __shared__ int   b_t[32];
    __shared__ int   s_istar;

    const unsigned FULL = 0xffffffffu;
    int tid  = threadIdx.x;
    int lane = tid & 31;
    int wid  = tid >> 5;
    bool live = (tid < NC);

    // ---- Independent early loads (all overlap) ----
    if (tid < 128) som[tid] = g_som[tid];           // stage omega table to SMEM
    unsigned long long S = g_sum;
    unsigned long long K = g_key;
    int   nm1 = g_nm1;
    float p0v = live ? p0[tid]   : -INFINITY;
    float ppv = live ? g_pp[tid] : 0.0f;

    int   c   = 1023 - (int)(K & 1023u);
    float p0c = __uint_as_float((unsigned)(K >> 32));
    if (tid == c) s_ppc = ppv;                      // broadcast pp[c] via SMEM
    __syncthreads();                                // barrier A: som + s_ppc

    float sumexp = (float)S * (1.0f / FPSCALE);
    float inv    = 1.0f / sumexp;
    float qv     = __expf(ppv) * inv;
    float qc     = __expf(s_ppc) * inv;             // bitwise == owner's qv
    float w0     = som[0];

    // ---- Local exact stop index t_j (no sync) ----
    // Violation (j beats c): j<c needs vj >= vc ; j>c needs vj > vc.
    // d(w) = (1-w)A + wB, A = p0c-p0j > 0.  No crossover => t=0.  Else real
    // crossover theta = A/(A-B); float transition lies within +-1 step
    // (margin 0.01*(A-B) >> float noise): 5-point exact float check starting
    // 2 steps early resolves t exactly.  Capped at nm1 (forced underflow).
    int t = 0;
    if (live && tid != c) {
        float A = p0c - p0v;
        float B = qc  - qv;
        bool cross = (tid < c) ? (B <= 0.0f) : (B < 0.0f);
        if (cross) {
            float theta = A / (A - B);
            int ie = (int)ceilf((w0 - theta) * 100.0f);
            int s0 = ie - 2;
            if (s0 < 0) s0 = 0;
            if (s0 > nm1) s0 = nm1;
            t = nm1;                        // default: violating to the end
            bool found = false;
            #pragma unroll
            for (int s = 0; s < 5; ++s) {
                int i = s0 + s;
                if (i > nm1) i = nm1;
                float cw   = som[i];        // SMEM, 29 cyc
                float onem = 1.0f - cw;
                float vc = onem * p0c + cw * qc;
                float vj = onem * p0v + cw * qv;
                bool viol = (tid < c) ? (vj >= vc) : (vj > vc);
                if (!found && !viol) { t = i; found = true; }
            }
        }
    }

    // ---- istar = max_j t_j : REDUX per warp, stage 2 on warp 0 ----
    {
        int m = __reduce_max_sync(FULL, t);
        if (lane == 0) b_t[wid] = m;
    }
    __syncthreads();                        // barrier B
    if (wid == 0) {
        int m = __reduce_max_sync(FULL, b_t[lane]);
        if (lane == 0) s_istar = m;
    }
    __syncthreads();                        // barrier C

    // ---- Output: p = (1-omega*) * p0 + omega* * q, shape (1, NC) ----
    float om = som[s_istar];                // SMEM broadcast
    if (live)
        out[tid] = (1.0f - om) * p0v + om * qv;

    // ---- Reset the additive accumulator for the next graph replay ----
    if (tid == 0) { g_sum = 0ULL; }
}

extern "C" void kernel_launch(void* const* d_in, const int* in_sizes, int n_in,
                              void* d_out, int out_size) {
    const float* p0 = (const float*)d_in[0];
    const float* P  = (const float*)d_in[1];
    const float* W  = (const float*)d_in[2];
    const float* om = (const float*)d_in[3];
    float* out = (float*)d_out;

    pp_kernel<<<126, 256>>>(W, P, p0, om);
    solve_kernel<<<1, 1024>>>(p0, out);
}